// round 12
// baseline (speedup 1.0000x reference)
#include <cuda_runtime.h>
#include <cuda_fp16.h>
#include <cstdint>

#define NNODES 2048
#define JDIM   768      // F_IN * T = 32*24
#define KCHEB  3
#define BATCH  16
#define FOUT   64
#define TDIM   24

// 302 MB scratch: rhs[b][m][k][f*24+t]
__device__ float g_rhs[(size_t)BATCH * NNODES * KCHEB * JDIM];
// 50 MB pre-packed x: half2{x[b][2np][j], x[b][2np+1][j]} at [b][np][j]
__device__ uint32_t g_xh[(size_t)BATCH * (NNODES / 2) * JDIM];

__device__ __forceinline__ uint32_t pack_h2(float lo, float hi) {
    __half2 h = __floats2half2_rn(lo, hi);
    return *reinterpret_cast<uint32_t*>(&h);
}
__device__ __forceinline__ uint32_t smem_u32(const void* p) {
    uint32_t a;
    asm("{ .reg .u64 t; cvta.to.shared.u64 t, %1; cvt.u32.u64 %0, t; }" : "=r"(a) : "l"(p));
    return a;
}
__device__ __forceinline__ void cp16(uint32_t dst, const void* src) {
    asm volatile("cp.async.ca.shared.global [%0], [%1], 16;" :: "r"(dst), "l"(src) : "memory");
}
__device__ __forceinline__ void mma_fp16(float d[4], const uint32_t a[4], const uint32_t b[2]) {
    asm("mma.sync.aligned.m16n8k16.row.col.f32.f16.f16.f32 "
        "{%0,%1,%2,%3}, {%4,%5,%6,%7}, {%8,%9}, {%0,%1,%2,%3};"
        : "+f"(d[0]), "+f"(d[1]), "+f"(d[2]), "+f"(d[3])
        : "r"(a[0]), "r"(a[1]), "r"(a[2]), "r"(a[3]),
          "r"(b[0]), "r"(b[1]));
}
// packed fp32x2 fma (Blackwell base ISA, PTX-only; ptxas never auto-fuses)
__device__ __forceinline__ void ffma2(uint64_t& d, uint64_t a, uint64_t b) {
    asm("fma.rn.f32x2 %0, %1, %2, %0;" : "+l"(d) : "l"(a), "l"(b));
}
__device__ __forceinline__ float2 u2f2(uint64_t u) {
    float2 f;
    asm("mov.b64 {%0,%1}, %2;" : "=f"(f.x), "=f"(f.y) : "l"(u));
    return f;
}

// ---------------------------------------------------------------------------
// Prepack: g_xh[b][np][j] = half2(x[b][2np][j], x[b][2np+1][j])
// ---------------------------------------------------------------------------
__global__ void __launch_bounds__(256)
prepack_kernel(const float* __restrict__ x)
{
    const int idx = blockIdx.x * 256 + threadIdx.x;   // over 16*1024*192 float4s
    const int b  = idx / (1024 * 192);
    const int r  = idx % (1024 * 192);
    const int np = r / 192;
    const int j4 = (r % 192) << 2;
    const size_t s0 = (size_t)(b * NNODES + (np << 1)) * JDIM + j4;
    const float4 a0 = *(const float4*)(x + s0);
    const float4 a1 = *(const float4*)(x + s0 + JDIM);
    uint4 o;
    o.x = pack_h2(a0.x, a1.x);  o.y = pack_h2(a0.y, a1.y);
    o.z = pack_h2(a0.z, a1.z);  o.w = pack_h2(a0.w, a1.w);
    *(uint4*)(g_xh + (size_t)(b * 1024 + np) * JDIM + j4) = o;
}

// ---------------------------------------------------------------------------
// Stage 1: per (k,b): rhs[m,j] = sum_n (cheb[k][n][m]*att[b][n][m]) * x[b][n][j]
// fp16 m16n8k16. CTA tile 128(m) x 256(j), K-chunk 32(n), 256 threads =
// 8 warps as 2(m) x 4(j); warp tile 64m x 64j. (~93% of mma issue floor.)
// ---------------------------------------------------------------------------
__global__ void __launch_bounds__(256)
stage1_kernel(const float* __restrict__ att,
              const float* __restrict__ cheb)
{
    const int k  = blockIdx.z % KCHEB;
    const int b  = blockIdx.z / KCHEB;
    const int m0 = blockIdx.y << 7;
    const int j0 = blockIdx.x << 8;

    const float* __restrict__ Ac = cheb + (size_t)k * NNODES * NNODES;
    const float* __restrict__ Aa = att  + (size_t)b * NNODES * NNODES;

    __shared__ __align__(16) uint32_t As[2][16][136];  // half2 prod, [np][m]
    __shared__ __align__(16) uint32_t Bs[2][16][264];  // half2 x,    [np][j]

    const int tid  = threadIdx.x;
    const int lane = tid & 31;
    const int warp = tid >> 5;
    const int wm = (warp >> 2) << 6;
    const int wj = (warp & 3) << 6;
    const int g  = lane >> 2;
    const int ti = lane & 3;

    float acc[4][8][4];
#pragma unroll
    for (int i = 0; i < 4; ++i)
#pragma unroll
        for (int j = 0; j < 8; ++j)
#pragma unroll
            for (int c = 0; c < 4; ++c) acc[i][j][c] = 0.0f;

    float4 rc0[2], rc1[2], ra0[2], ra1[2];

    auto loadA = [&](int c) {
        const int n0 = c << 5;
#pragma unroll
        for (int i = 0; i < 2; ++i) {
            const int u  = tid + (i << 8);
            const int np = u >> 5;
            const int q  = u & 31;
            const size_t ro = (size_t)(n0 + (np << 1)) * NNODES + m0;
            rc0[i] = *((const float4*)(Ac + ro) + q);
            rc1[i] = *((const float4*)(Ac + ro + NNODES) + q);
            ra0[i] = *((const float4*)(Aa + ro) + q);
            ra1[i] = *((const float4*)(Aa + ro + NNODES) + q);
        }
    };
    auto storeA = [&](int nb) {
#pragma unroll
        for (int i = 0; i < 2; ++i) {
            const int u  = tid + (i << 8);
            const int np = u >> 5;
            const int q  = u & 31;
            uint4 ua;
            ua.x = pack_h2(rc0[i].x * ra0[i].x, rc1[i].x * ra1[i].x);
            ua.y = pack_h2(rc0[i].y * ra0[i].y, rc1[i].y * ra1[i].y);
            ua.z = pack_h2(rc0[i].z * ra0[i].z, rc1[i].z * ra1[i].z);
            ua.w = pack_h2(rc0[i].w * ra0[i].w, rc1[i].w * ra1[i].w);
            *(uint4*)&As[nb][np][q << 2] = ua;
        }
    };
    auto loadB = [&](int c, int nb) {
        const uint32_t base = smem_u32(&Bs[nb][0][0]);
        const uint32_t* src = g_xh + (size_t)(b * 1024 + (c << 4)) * JDIM + j0;
#pragma unroll
        for (int i = 0; i < 4; ++i) {
            const int l  = tid + (i << 8);
            const int np = l >> 6;
            const int o4 = (l & 63) << 2;
            cp16(base + (uint32_t)(np * 264 + o4) * 4, src + np * JDIM + o4);
        }
        asm volatile("cp.async.commit_group;" ::: "memory");
    };

    auto compute = [&](int buf) {
#pragma unroll
        for (int s = 0; s < 2; ++s) {
            const int r0 = (s << 3) + ti;
            const int r1 = r0 + 4;
            uint32_t af[4][4], bf[8][2];
#pragma unroll
            for (int i = 0; i < 4; ++i) {
                const int mi = wm + (i << 4);
                af[i][0] = As[buf][r0][mi + g];
                af[i][1] = As[buf][r0][mi + g + 8];
                af[i][2] = As[buf][r1][mi + g];
                af[i][3] = As[buf][r1][mi + g + 8];
            }
#pragma unroll
            for (int j = 0; j < 8; ++j) {
                const int nj = wj + (j << 3);
                bf[j][0] = Bs[buf][r0][nj + g];
                bf[j][1] = Bs[buf][r1][nj + g];
            }
#pragma unroll
            for (int i = 0; i < 4; ++i)
#pragma unroll
                for (int j = 0; j < 8; ++j)
                    mma_fp16(acc[i][j], af[i], bf[j]);
        }
    };

    loadA(0);
    loadB(0, 0);
    storeA(0);
    asm volatile("cp.async.wait_group 0;" ::: "memory");
    __syncthreads();

    for (int c = 0; c < 64; ++c) {
        const int buf = c & 1, nb = buf ^ 1;
        if (c < 63) {
            loadB(c + 1, nb);
            loadA(c + 1);
        }
        compute(buf);
        if (c < 63) {
            storeA(nb);
            asm volatile("cp.async.wait_group 0;" ::: "memory");
        }
        __syncthreads();
    }

#pragma unroll
    for (int i = 0; i < 4; ++i) {
#pragma unroll
        for (int h = 0; h < 2; ++h) {
            const int row = m0 + wm + (i << 4) + g + (h << 3);
            float* orow = g_rhs
                        + (((size_t)b * NNODES + row) * KCHEB + k) * JDIM
                        + j0 + wj + (ti << 1);
#pragma unroll
            for (int j = 0; j < 8; ++j) {
                float2 v = make_float2(acc[i][j][h << 1], acc[i][j][(h << 1) + 1]);
                *(float2*)(orow + (j << 3)) = v;
            }
        }
    }
}

// ---------------------------------------------------------------------------
// Stage 2: out[b,m,o,t] = relu( sum_{kf} rhs[b,m,kf,t] * Theta[kf,o] )
// 256 threads = 8 warps; each warp owns ONE (b,m) row. Lane = 8 o-thr x 4 t-thr,
// thread tile 8o x 6t held as u64 f32x2 accumulators; Theta pre-duplicated
// (w,w) in 48KB smem; rhs streamed from gmem (broadcast across o-lanes).
// ---------------------------------------------------------------------------
__global__ void __launch_bounds__(256)
stage2_kernel(const float* __restrict__ Theta, float* __restrict__ out)
{
    __shared__ float2 sW2[96 * 64];   // exactly 48 KB: sW2[kf*64+o] = (w,w)

    const int tid = threadIdx.x;
#pragma unroll
    for (int i = 0; i < 24; ++i) {
        const int l = tid + (i << 8);
        const float w = Theta[l];
        sW2[l] = make_float2(w, w);
    }
    __syncthreads();

    const size_t row = (size_t)blockIdx.x * 8 + (tid >> 5);  // one row per warp
    const int lane = tid & 31;
    const int o0 = (lane & 7) << 3;          // 8 consecutive o
    const int tb = (lane >> 3) * 6;          // 6 consecutive t
    const float* __restrict__ R = g_rhs + row * (KCHEB * JDIM);

    uint64_t acc[8][3];
#pragma unroll
    for (int i = 0; i < 8; ++i)
#pragma unroll
        for (int j = 0; j < 3; ++j) acc[i][j] = 0ull;

#pragma unroll 4
    for (int kf = 0; kf < 96; ++kf) {
        const ulonglong2* wp = (const ulonglong2*)(sW2 + (kf << 6) + o0);
        const ulonglong2 wq0 = wp[0], wq1 = wp[1], wq2 = wp[2], wq3 = wp[3];
        const uint64_t* rp = (const uint64_t*)(R + kf * TDIM + tb);
        const uint64_t r0 = rp[0], r1 = rp[1], r2 = rp[2];

        ffma2(acc[0][0], wq0.x, r0); ffma2(acc[0][1], wq0.x, r1); ffma2(acc[0][2], wq0.x, r2);
        ffma2(acc[1][0], wq0.y, r0); ffma2(acc[1][1], wq0.y, r1); ffma2(acc[1][2], wq0.y, r2);
        ffma2(acc[2][0], wq1.x, r0); ffma2(acc[2][1], wq1.x, r1); ffma2(acc[2][2], wq1.x, r2);
        ffma2(acc[3][0], wq1.y, r0); ffma2(acc[3][1], wq1.y, r1); ffma2(acc[3][2], wq1.y, r2);
        ffma2(acc[4][0], wq2.x, r0); ffma2(acc[4][1], wq2.x, r1); ffma2(acc[4][2], wq2.x, r2);
        ffma2(acc[5][0], wq2.y, r0); ffma2(acc[5][1], wq2.y, r1); ffma2(acc[5][2], wq2.y, r2);
        ffma2(acc[6][0], wq3.x, r0); ffma2(acc[6][1], wq3.x, r1); ffma2(acc[6][2], wq3.x, r2);
        ffma2(acc[7][0], wq3.y, r0); ffma2(acc[7][1], wq3.y, r1); ffma2(acc[7][2], wq3.y, r2);
    }

    float* obase = out + row * (FOUT * TDIM);
#pragma unroll
    for (int i = 0; i < 8; ++i) {
        float* orow = obase + (o0 + i) * TDIM + tb;
#pragma unroll
        for (int j = 0; j < 3; ++j) {
            float2 v = u2f2(acc[i][j]);
            v.x = fmaxf(v.x, 0.0f);
            v.y = fmaxf(v.y, 0.0f);
            *(float2*)(orow + (j << 1)) = v;
        }
    }
}

// ---------------------------------------------------------------------------
extern "C" void kernel_launch(void* const* d_in, const int* in_sizes, int n_in,
                              void* d_out, int out_size)
{
    (void)in_sizes; (void)n_in; (void)out_size;
    const float* x     = (const float*)d_in[0];   // (16,2048,32,24)
    const float* att   = (const float*)d_in[1];   // (16,2048,2048)
    const float* cheb  = (const float*)d_in[2];   // (3,2048,2048)
    const float* Theta = (const float*)d_in[3];   // (3,32,64)
    float* out = (float*)d_out;                   // (16,2048,64,24)

    prepack_kernel<<<BATCH * 1024 * 192 / 256, 256>>>(x);
    dim3 g1(JDIM / 256, NNODES / 128, KCHEB * BATCH);   // (3, 16, 48)
    stage1_kernel<<<g1, 256>>>(att, cheb);
    stage2_kernel<<<(BATCH * NNODES) / 8, 256>>>(Theta, out);
}

// round 13
// speedup vs baseline: 1.2739x; 1.2739x over previous
#include <cuda_runtime.h>
#include <cuda_fp16.h>
#include <cstdint>

#define NNODES 2048
#define JDIM   768      // F_IN * T = 32*24
#define KCHEB  3
#define BATCH  16
#define FOUT   64
#define TDIM   24

// 302 MB scratch: rhs[b][m][k][f*24+t]
__device__ float g_rhs[(size_t)BATCH * NNODES * KCHEB * JDIM];
// 50 MB pre-packed x: half2{x[b][2np][j], x[b][2np+1][j]} at [b][np][j]
__device__ uint32_t g_xh[(size_t)BATCH * (NNODES / 2) * JDIM];

__device__ __forceinline__ uint32_t pack_h2(float lo, float hi) {
    __half2 h = __floats2half2_rn(lo, hi);
    return *reinterpret_cast<uint32_t*>(&h);
}
__device__ __forceinline__ uint32_t smem_u32(const void* p) {
    uint32_t a;
    asm("{ .reg .u64 t; cvta.to.shared.u64 t, %1; cvt.u32.u64 %0, t; }" : "=r"(a) : "l"(p));
    return a;
}
__device__ __forceinline__ void cp16(uint32_t dst, const void* src) {
    asm volatile("cp.async.ca.shared.global [%0], [%1], 16;" :: "r"(dst), "l"(src) : "memory");
}
__device__ __forceinline__ void mma_fp16(float d[4], const uint32_t a[4], const uint32_t b[2]) {
    asm("mma.sync.aligned.m16n8k16.row.col.f32.f16.f16.f32 "
        "{%0,%1,%2,%3}, {%4,%5,%6,%7}, {%8,%9}, {%0,%1,%2,%3};"
        : "+f"(d[0]), "+f"(d[1]), "+f"(d[2]), "+f"(d[3])
        : "r"(a[0]), "r"(a[1]), "r"(a[2]), "r"(a[3]),
          "r"(b[0]), "r"(b[1]));
}
// packed fp32x2 fma (Blackwell base ISA, PTX-only)
__device__ __forceinline__ void ffma2(uint64_t& d, uint64_t a, uint64_t b) {
    asm("fma.rn.f32x2 %0, %1, %2, %0;" : "+l"(d) : "l"(a), "l"(b));
}
__device__ __forceinline__ float2 u2f2(uint64_t u) {
    float2 f;
    asm("mov.b64 {%0,%1}, %2;" : "=f"(f.x), "=f"(f.y) : "l"(u));
    return f;
}

// ---------------------------------------------------------------------------
// Prepack: g_xh[b][np][j] = half2(x[b][2np][j], x[b][2np+1][j])
// ---------------------------------------------------------------------------
__global__ void __launch_bounds__(256)
prepack_kernel(const float* __restrict__ x)
{
    const int idx = blockIdx.x * 256 + threadIdx.x;
    const int b  = idx / (1024 * 192);
    const int r  = idx % (1024 * 192);
    const int np = r / 192;
    const int j4 = (r % 192) << 2;
    const size_t s0 = (size_t)(b * NNODES + (np << 1)) * JDIM + j4;
    const float4 a0 = *(const float4*)(x + s0);
    const float4 a1 = *(const float4*)(x + s0 + JDIM);
    uint4 o;
    o.x = pack_h2(a0.x, a1.x);  o.y = pack_h2(a0.y, a1.y);
    o.z = pack_h2(a0.z, a1.z);  o.w = pack_h2(a0.w, a1.w);
    *(uint4*)(g_xh + (size_t)(b * 1024 + np) * JDIM + j4) = o;
}

// ---------------------------------------------------------------------------
// Stage 1 (unchanged — measured at 96% of the fp16 mma issue floor)
// ---------------------------------------------------------------------------
__global__ void __launch_bounds__(256)
stage1_kernel(const float* __restrict__ att,
              const float* __restrict__ cheb)
{
    const int k  = blockIdx.z % KCHEB;
    const int b  = blockIdx.z / KCHEB;
    const int m0 = blockIdx.y << 7;
    const int j0 = blockIdx.x << 8;

    const float* __restrict__ Ac = cheb + (size_t)k * NNODES * NNODES;
    const float* __restrict__ Aa = att  + (size_t)b * NNODES * NNODES;

    __shared__ __align__(16) uint32_t As[2][16][136];
    __shared__ __align__(16) uint32_t Bs[2][16][264];

    const int tid  = threadIdx.x;
    const int lane = tid & 31;
    const int warp = tid >> 5;
    const int wm = (warp >> 2) << 6;
    const int wj = (warp & 3) << 6;
    const int g  = lane >> 2;
    const int ti = lane & 3;

    float acc[4][8][4];
#pragma unroll
    for (int i = 0; i < 4; ++i)
#pragma unroll
        for (int j = 0; j < 8; ++j)
#pragma unroll
            for (int c = 0; c < 4; ++c) acc[i][j][c] = 0.0f;

    float4 rc0[2], rc1[2], ra0[2], ra1[2];

    auto loadA = [&](int c) {
        const int n0 = c << 5;
#pragma unroll
        for (int i = 0; i < 2; ++i) {
            const int u  = tid + (i << 8);
            const int np = u >> 5;
            const int q  = u & 31;
            const size_t ro = (size_t)(n0 + (np << 1)) * NNODES + m0;
            rc0[i] = *((const float4*)(Ac + ro) + q);
            rc1[i] = *((const float4*)(Ac + ro + NNODES) + q);
            ra0[i] = *((const float4*)(Aa + ro) + q);
            ra1[i] = *((const float4*)(Aa + ro + NNODES) + q);
        }
    };
    auto storeA = [&](int nb) {
#pragma unroll
        for (int i = 0; i < 2; ++i) {
            const int u  = tid + (i << 8);
            const int np = u >> 5;
            const int q  = u & 31;
            uint4 ua;
            ua.x = pack_h2(rc0[i].x * ra0[i].x, rc1[i].x * ra1[i].x);
            ua.y = pack_h2(rc0[i].y * ra0[i].y, rc1[i].y * ra1[i].y);
            ua.z = pack_h2(rc0[i].z * ra0[i].z, rc1[i].z * ra1[i].z);
            ua.w = pack_h2(rc0[i].w * ra0[i].w, rc1[i].w * ra1[i].w);
            *(uint4*)&As[nb][np][q << 2] = ua;
        }
    };
    auto loadB = [&](int c, int nb) {
        const uint32_t base = smem_u32(&Bs[nb][0][0]);
        const uint32_t* src = g_xh + (size_t)(b * 1024 + (c << 4)) * JDIM + j0;
#pragma unroll
        for (int i = 0; i < 4; ++i) {
            const int l  = tid + (i << 8);
            const int np = l >> 6;
            const int o4 = (l & 63) << 2;
            cp16(base + (uint32_t)(np * 264 + o4) * 4, src + np * JDIM + o4);
        }
        asm volatile("cp.async.commit_group;" ::: "memory");
    };

    auto compute = [&](int buf) {
#pragma unroll
        for (int s = 0; s < 2; ++s) {
            const int r0 = (s << 3) + ti;
            const int r1 = r0 + 4;
            uint32_t af[4][4], bf[8][2];
#pragma unroll
            for (int i = 0; i < 4; ++i) {
                const int mi = wm + (i << 4);
                af[i][0] = As[buf][r0][mi + g];
                af[i][1] = As[buf][r0][mi + g + 8];
                af[i][2] = As[buf][r1][mi + g];
                af[i][3] = As[buf][r1][mi + g + 8];
            }
#pragma unroll
            for (int j = 0; j < 8; ++j) {
                const int nj = wj + (j << 3);
                bf[j][0] = Bs[buf][r0][nj + g];
                bf[j][1] = Bs[buf][r1][nj + g];
            }
#pragma unroll
            for (int i = 0; i < 4; ++i)
#pragma unroll
                for (int j = 0; j < 8; ++j)
                    mma_fp16(acc[i][j], af[i], bf[j]);
        }
    };

    loadA(0);
    loadB(0, 0);
    storeA(0);
    asm volatile("cp.async.wait_group 0;" ::: "memory");
    __syncthreads();

    for (int c = 0; c < 64; ++c) {
        const int buf = c & 1, nb = buf ^ 1;
        if (c < 63) {
            loadB(c + 1, nb);
            loadA(c + 1);
        }
        compute(buf);
        if (c < 63) {
            storeA(nb);
            asm volatile("cp.async.wait_group 0;" ::: "memory");
        }
        __syncthreads();
    }

#pragma unroll
    for (int i = 0; i < 4; ++i) {
#pragma unroll
        for (int h = 0; h < 2; ++h) {
            const int row = m0 + wm + (i << 4) + g + (h << 3);
            float* orow = g_rhs
                        + (((size_t)b * NNODES + row) * KCHEB + k) * JDIM
                        + j0 + wj + (ti << 1);
#pragma unroll
            for (int j = 0; j < 8; ++j) {
                float2 v = make_float2(acc[i][j][h << 1], acc[i][j][(h << 1) + 1]);
                *(float2*)(orow + (j << 3)) = v;
            }
        }
    }
}

// ---------------------------------------------------------------------------
// Stage 2 v3: out[b,m,o,t] = relu( sum_{kf} rhs[b,m,kf,t] * Theta[kf,o] )
// 512 threads = 16 warps, ONE row per warp, 16 rows staged in smem (147 KB).
// Thread tile 8o x 6t; accumulators are f32x2 pairs over (t,t+1) so rhs pairs
// load directly as u64. Theta duplicated (w,w) in a 9-per-8 padded u64 layout
// -> the 8 w loads per kf are consecutive u64s on distinct banks.
// Per warp per kf: 8+3 conflict-free LDS.64 + 24 FFMA2.
// ---------------------------------------------------------------------------
#define S2_ROWS    16
#define S2_WBYTES  (96 * 72 * 8)                     // 55296
#define S2_SMEM    (S2_WBYTES + S2_ROWS * KCHEB * JDIM * 4)   // 202752

__global__ void __launch_bounds__(512)
stage2_kernel(const float* __restrict__ Theta, float* __restrict__ out)
{
    extern __shared__ __align__(16) char s2[];
    uint64_t* sWu = (uint64_t*)s2;                   // [96][72] padded dup'd Theta
    float*    sR  = (float*)(s2 + S2_WBYTES);        // [16][2304]

    const int tid = threadIdx.x;

    // duplicate Theta into padded slots: slot = kf*72 + o + (o>>3)
#pragma unroll
    for (int i = 0; i < 12; ++i) {
        const int l  = tid + (i << 9);               // 0..6143
        const int kf = l >> 6, o = l & 63;
        const uint32_t u = __float_as_uint(Theta[l]);
        sWu[kf * 72 + o + (o >> 3)] = ((uint64_t)u << 32) | (uint64_t)u;
    }
    // stage 16 rhs rows, coalesced float4
    const size_t row0 = (size_t)blockIdx.x * S2_ROWS;
    const float4* rsrc = (const float4*)(g_rhs + row0 * (KCHEB * JDIM));
    float4* rdst = (float4*)sR;
#pragma unroll
    for (int i = 0; i < 18; ++i) {
        const int l = tid + (i << 9);                // 0..9215
        rdst[l] = rsrc[l];
    }
    __syncthreads();

    const int w    = tid >> 5;
    const int lane = tid & 31;
    const int g    = lane & 7;          // o group: o = 8g..8g+7
    const int tb   = (lane >> 3) * 6;   // t base: 0,6,12,18
    const float* R = sR + w * (KCHEB * JDIM);

    uint64_t acc[8][3];
#pragma unroll
    for (int i = 0; i < 8; ++i)
#pragma unroll
        for (int j = 0; j < 3; ++j) acc[i][j] = 0ull;

#pragma unroll 4
    for (int kf = 0; kf < 96; ++kf) {
        const uint64_t* wp = sWu + kf * 72 + 9 * g;  // 8 consecutive u64 slots
        uint64_t wq[8];
#pragma unroll
        for (int i = 0; i < 8; ++i) wq[i] = wp[i];
        const uint64_t* rp = (const uint64_t*)(R + kf * TDIM + tb);
        const uint64_t r0 = rp[0], r1 = rp[1], r2 = rp[2];
#pragma unroll
        for (int i = 0; i < 8; ++i) {
            ffma2(acc[i][0], wq[i], r0);
            ffma2(acc[i][1], wq[i], r1);
            ffma2(acc[i][2], wq[i], r2);
        }
    }

    float* obase = out + (row0 + w) * (FOUT * TDIM);
#pragma unroll
    for (int i = 0; i < 8; ++i) {
        float* orow = obase + ((g << 3) + i) * TDIM + tb;
#pragma unroll
        for (int j = 0; j < 3; ++j) {
            float2 v = u2f2(acc[i][j]);
            v.x = fmaxf(v.x, 0.0f);
            v.y = fmaxf(v.y, 0.0f);
            *(float2*)(orow + (j << 1)) = v;
        }
    }
}

// ---------------------------------------------------------------------------
extern "C" void kernel_launch(void* const* d_in, const int* in_sizes, int n_in,
                              void* d_out, int out_size)
{
    (void)in_sizes; (void)n_in; (void)out_size;
    const float* x     = (const float*)d_in[0];   // (16,2048,32,24)
    const float* att   = (const float*)d_in[1];   // (16,2048,2048)
    const float* cheb  = (const float*)d_in[2];   // (3,2048,2048)
    const float* Theta = (const float*)d_in[3];   // (3,32,64)
    float* out = (float*)d_out;                   // (16,2048,64,24)

    cudaFuncSetAttribute(stage2_kernel,
                         cudaFuncAttributeMaxDynamicSharedMemorySize, S2_SMEM);

    prepack_kernel<<<BATCH * 1024 * 192 / 256, 256>>>(x);
    dim3 g1(JDIM / 256, NNODES / 128, KCHEB * BATCH);   // (3, 16, 48)
    stage1_kernel<<<g1, 256>>>(att, cheb);
    stage2_kernel<<<(BATCH * NNODES) / S2_ROWS, 512, S2_SMEM>>>(Theta, out);
}